// round 2
// baseline (speedup 1.0000x reference)
#include <cuda_runtime.h>
#include <cstdint>

#define B_IMG 128
#define B_CAP 128
#define R 64
#define W 64
#define D 128

#define A_PITCH 132      // 64x128 tile padded: 132 mod 32 = 4 -> conflict-free frag loads
#define S_PITCH 68       // sims pitch: 68 mod 32 = 4 -> conflict-free row & col reads

#define SMEM_FLOATS (2 * 64 * A_PITCH + 64 * S_PITCH + 128)
#define SMEM_BYTES  (SMEM_FLOATS * 4)

__device__ __forceinline__ uint32_t f2tf32(float x) {
    uint32_t r;
    asm("cvt.rna.tf32.f32 %0, %1;" : "=r"(r) : "f"(x));
    return r;
}

#define MMA_TF32(d, a, b)                                                     \
    asm volatile(                                                             \
        "mma.sync.aligned.m16n8k8.row.col.f32.tf32.tf32.f32 "                 \
        "{%0,%1,%2,%3}, {%4,%5,%6,%7}, {%8,%9}, {%0,%1,%2,%3};\n"             \
        : "+f"(d[0]), "+f"(d[1]), "+f"(d[2]), "+f"(d[3])                      \
        : "r"(a[0]), "r"(a[1]), "r"(a[2]), "r"(a[3]), "r"(b[0]), "r"(b[1]))

__global__ __launch_bounds__(128) void select_kernel(
    const float* __restrict__ imgs, const float* __restrict__ caps,
    const int* __restrict__ img_lens, const int* __restrict__ cap_lens,
    float* __restrict__ out)
{
    extern __shared__ float sm[];
    float* As  = sm;                       // [64][A_PITCH] tf32 bits of imgs[i]
    float* Bs  = sm + 64 * A_PITCH;        // [64][A_PITCH] tf32 bits of caps[t]
    float* Ss  = sm + 2 * 64 * A_PITCH;    // [64][S_PITCH] masked sims
    float* red = Ss + 64 * S_PITCH;        // [128] row/col partial sums

    const int i   = blockIdx.y;
    const int t   = blockIdx.x;
    const int tid = threadIdx.x;

    const int nv = __ldg(img_lens + i);
    const int nt = __ldg(cap_lens + t);

    // ---- Phase 1: load + convert to tf32 (RNA) into padded smem ----
    {
        const float4* gi = (const float4*)(imgs + (size_t)i * R * D);
        const float4* gc = (const float4*)(caps + (size_t)t * W * D);
        #pragma unroll
        for (int j = tid; j < R * D / 4; j += 128) {
            float4 v = gi[j];
            int row = j >> 5, c4 = (j & 31) << 2;   // 32 float4 per 128-wide row
            float4 w;
            w.x = __uint_as_float(f2tf32(v.x));
            w.y = __uint_as_float(f2tf32(v.y));
            w.z = __uint_as_float(f2tf32(v.z));
            w.w = __uint_as_float(f2tf32(v.w));
            *(float4*)(As + row * A_PITCH + c4) = w;
        }
        #pragma unroll
        for (int j = tid; j < W * D / 4; j += 128) {
            float4 v = gc[j];
            int row = j >> 5, c4 = (j & 31) << 2;
            float4 w;
            w.x = __uint_as_float(f2tf32(v.x));
            w.y = __uint_as_float(f2tf32(v.y));
            w.z = __uint_as_float(f2tf32(v.z));
            w.w = __uint_as_float(f2tf32(v.w));
            *(float4*)(Bs + row * A_PITCH + c4) = w;
        }
    }
    __syncthreads();

    // ---- Phase 2: 64x64x128 GEMM via m16n8k8 tf32 mma, 4 warps (32x32 each) ----
    {
        const int warp  = tid >> 5;
        const int lane  = tid & 31;
        const int g     = lane >> 2;   // groupID
        const int t4    = lane & 3;    // threadID in group
        const int warpM = (warp >> 1) * 32;
        const int warpN = (warp & 1) * 32;

        float acc[2][4][4];
        #pragma unroll
        for (int mi = 0; mi < 2; ++mi)
            #pragma unroll
            for (int ni = 0; ni < 4; ++ni)
                #pragma unroll
                for (int q = 0; q < 4; ++q) acc[mi][ni][q] = 0.0f;

        #pragma unroll
        for (int kk = 0; kk < D; kk += 8) {
            uint32_t a[2][4], b[4][2];
            #pragma unroll
            for (int mi = 0; mi < 2; ++mi) {
                const float* ap = As + (warpM + mi * 16 + g) * A_PITCH + kk + t4;
                a[mi][0] = __float_as_uint(ap[0]);
                a[mi][1] = __float_as_uint(ap[8 * A_PITCH]);
                a[mi][2] = __float_as_uint(ap[4]);
                a[mi][3] = __float_as_uint(ap[8 * A_PITCH + 4]);
            }
            #pragma unroll
            for (int ni = 0; ni < 4; ++ni) {
                const float* bp = Bs + (warpN + ni * 8 + g) * A_PITCH + kk + t4;
                b[ni][0] = __float_as_uint(bp[0]);
                b[ni][1] = __float_as_uint(bp[4]);
            }
            #pragma unroll
            for (int mi = 0; mi < 2; ++mi)
                #pragma unroll
                for (int ni = 0; ni < 4; ++ni)
                    MMA_TF32(acc[mi][ni], a[mi], b[ni]);
        }

        // epilogue: apply mask (-1 outside lens) and store to smem sims
        #pragma unroll
        for (int mi = 0; mi < 2; ++mi) {
            #pragma unroll
            for (int ni = 0; ni < 4; ++ni) {
                int r0 = warpM + mi * 16 + g;
                int r1 = r0 + 8;
                int c0 = warpN + ni * 8 + 2 * t4;
                bool cv0 = (c0 < nt), cv1 = (c0 + 1 < nt);
                Ss[r0 * S_PITCH + c0]     = (r0 < nv && cv0) ? acc[mi][ni][0] : -1.0f;
                Ss[r0 * S_PITCH + c0 + 1] = (r0 < nv && cv1) ? acc[mi][ni][1] : -1.0f;
                Ss[r1 * S_PITCH + c0]     = (r1 < nv && cv0) ? acc[mi][ni][2] : -1.0f;
                Ss[r1 * S_PITCH + c0 + 1] = (r1 < nv && cv1) ? acc[mi][ni][3] : -1.0f;
            }
        }
    }
    __syncthreads();

    // ---- Phase 3: sparsemax per row (tid<64) / per column (tid>=64) ----
    {
        const float* bp;
        int str;
        if (tid < 64) { bp = Ss + tid * S_PITCH; str = 1; }        // region -> words
        else          { bp = Ss + (tid - 64);    str = S_PITCH; }  // word -> regions

        float z[64];
        #pragma unroll
        for (int j = 0; j < 64; ++j) z[j] = bp[j * str];

        // initial tau from full support
        float s0 = 0.f, s1 = 0.f, s2 = 0.f, s3 = 0.f;
        #pragma unroll
        for (int j = 0; j < 64; j += 4) {
            s0 += z[j]; s1 += z[j + 1]; s2 += z[j + 2]; s3 += z[j + 3];
        }
        float tau = ((s0 + s1) + (s2 + s3) - 1.0f) * (1.0f / 64.0f);
        int k = 64;

        // Michelot fixed-point: tau is monotone nondecreasing, support nested
        #pragma unroll 1
        for (int it = 0; it < 64; ++it) {
            float a0 = 0.f, a1 = 0.f, a2 = 0.f, a3 = 0.f;
            int c = 0;
            #pragma unroll
            for (int j = 0; j < 64; j += 4) {
                if (z[j]     > tau) { a0 += z[j];     c++; }
                if (z[j + 1] > tau) { a1 += z[j + 1]; c++; }
                if (z[j + 2] > tau) { a2 += z[j + 2]; c++; }
                if (z[j + 3] > tau) { a3 += z[j + 3]; c++; }
            }
            if (c == k) break;           // support unchanged -> tau is the fixpoint
            k = c;
            tau = __fdividef(((a0 + a1) + (a2 + a3)) - 1.0f, (float)c);
        }

        // sum_j max(z_j - tau, 0) * z_j
        float a0 = 0.f, a1 = 0.f, a2 = 0.f, a3 = 0.f;
        #pragma unroll
        for (int j = 0; j < 64; j += 4) {
            float p0 = z[j] - tau,     p1 = z[j + 1] - tau;
            float p2 = z[j + 2] - tau, p3 = z[j + 3] - tau;
            if (p0 > 0.f) a0 = fmaf(p0, z[j],     a0);
            if (p1 > 0.f) a1 = fmaf(p1, z[j + 1], a1);
            if (p2 > 0.f) a2 = fmaf(p2, z[j + 2], a2);
            if (p3 > 0.f) a3 = fmaf(p3, z[j + 3], a3);
        }
        float rsum = (a0 + a1) + (a2 + a3);

        // mask out rows/cols beyond lens (their marginal weight is 0)
        bool valid = (tid < 64) ? (tid < nv) : ((tid - 64) < nt);
        red[tid] = valid ? rsum : 0.0f;
    }
    __syncthreads();

    // ---- Phase 4: masked means, output ----
    if (tid < 32) {
        float v = red[tid] + red[tid + 32];            // rows:   v2t numerator
        float w = red[64 + tid] + red[96 + tid];       // cols:   t2v numerator
        #pragma unroll
        for (int o = 16; o; o >>= 1) {
            v += __shfl_down_sync(0xffffffffu, v, o);
            w += __shfl_down_sync(0xffffffffu, w, o);
        }
        if (tid == 0)
            out[i * B_CAP + t] = 0.5f * (v / (float)nv + w / (float)nt);
    }
}

extern "C" void kernel_launch(void* const* d_in, const int* in_sizes, int n_in,
                              void* d_out, int out_size)
{
    // metadata order: img_cls, imgs, cap_cls, caps, img_lens, cap_lens
    const float* imgs     = (const float*)d_in[1];
    const float* caps     = (const float*)d_in[3];
    const int*   img_lens = (const int*)d_in[4];
    const int*   cap_lens = (const int*)d_in[5];
    float*       out      = (float*)d_out;

    cudaFuncSetAttribute(select_kernel,
                         cudaFuncAttributeMaxDynamicSharedMemorySize, SMEM_BYTES);

    dim3 grid(B_CAP, B_IMG);
    select_kernel<<<grid, 128, SMEM_BYTES>>>(imgs, caps, img_lens, cap_lens, out);
}

// round 3
// speedup vs baseline: 1.1908x; 1.1908x over previous
#include <cuda_runtime.h>
#include <cstdint>

#define B_IMG 128
#define B_CAP 128
#define R 64
#define W 64
#define D 128

#define A_PITCH 132            // (4g + t4) distinct mod 32 -> conflict-free frag loads
#define S_PITCH 65             // stride 1 across threads -> conflict-free rows AND cols
#define TILE_F  (64 * A_PITCH) // 8448 floats per operand tile
#define SS_F    (64 * S_PITCH) // 4160 floats per sims tile (2 overlay into As: 8320<=8448)

#define SMEM_FLOATS (3 * TILE_F + 256)
#define SMEM_BYTES  (SMEM_FLOATS * 4)   // 100 KB -> 2 CTAs/SM

__device__ __forceinline__ uint32_t f2tf32(float x) {
    uint32_t r;
    asm("cvt.rna.tf32.f32 %0, %1;" : "=r"(r) : "f"(x));
    return r;
}

#define MMA_TF32(d, a, b)                                                     \
    asm volatile(                                                             \
        "mma.sync.aligned.m16n8k8.row.col.f32.tf32.tf32.f32 "                 \
        "{%0,%1,%2,%3}, {%4,%5,%6,%7}, {%8,%9}, {%0,%1,%2,%3};\n"             \
        : "+f"(d[0]), "+f"(d[1]), "+f"(d[2]), "+f"(d[3])                      \
        : "r"(a[0]), "r"(a[1]), "r"(a[2]), "r"(a[3]), "r"(b[0]), "r"(b[1]))

// One CTA = 1 image x 2 captions. 256 threads.
// Warps 0-3 -> pair 0 GEMM, warps 4-7 -> pair 1 GEMM (each warp 32x32 of 64x64).
__global__ __launch_bounds__(256) void select_kernel(
    const float* __restrict__ imgs, const float* __restrict__ caps,
    const int* __restrict__ img_lens, const int* __restrict__ cap_lens,
    float* __restrict__ out)
{
    extern __shared__ float sm[];
    float* As  = sm;                    // [64][A_PITCH] tf32 imgs tile
    float* Bs0 = sm + TILE_F;           // [64][A_PITCH] tf32 caps tile, pair 0
    // Bs1 = Bs0 + TILE_F               // pair 1
    // Ss(p) = sm + p*SS_F              // overlays As after GEMM
    float* red = sm + 3 * TILE_F;       // [256]

    const int i   = blockIdx.y;
    const int t0  = blockIdx.x * 2;
    const int tid = threadIdx.x;

    const int nv  = __ldg(img_lens + i);
    const int nt0 = __ldg(cap_lens + t0);
    const int nt1 = __ldg(cap_lens + t0 + 1);

    // ---- Phase 1: load + tf32-convert into padded smem ----
    {
        const float4* gi = (const float4*)(imgs + (size_t)i * R * D);
        const float4* gc = (const float4*)(caps + (size_t)t0 * W * D); // 2 tiles contiguous
        #pragma unroll
        for (int j = tid; j < R * D / 4; j += 256) {
            float4 v = gi[j];
            int row = j >> 5, c4 = (j & 31) << 2;
            float4 w;
            w.x = __uint_as_float(f2tf32(v.x));
            w.y = __uint_as_float(f2tf32(v.y));
            w.z = __uint_as_float(f2tf32(v.z));
            w.w = __uint_as_float(f2tf32(v.w));
            *(float4*)(As + row * A_PITCH + c4) = w;
        }
        #pragma unroll
        for (int j = tid; j < 2 * W * D / 4; j += 256) {
            float4 v = gc[j];
            int p = j >> 11;                    // which caption tile
            int jj = j & 2047;
            int row = jj >> 5, c4 = (jj & 31) << 2;
            float4 w;
            w.x = __uint_as_float(f2tf32(v.x));
            w.y = __uint_as_float(f2tf32(v.y));
            w.z = __uint_as_float(f2tf32(v.z));
            w.w = __uint_as_float(f2tf32(v.w));
            *(float4*)(Bs0 + p * TILE_F + row * A_PITCH + c4) = w;
        }
    }
    __syncthreads();

    // ---- Phase 2: per pair 64x64x128 GEMM via m16n8k8 tf32 mma ----
    {
        const int warp = tid >> 5;
        const int lane = tid & 31;
        const int p    = warp >> 2;        // pair
        const int w4   = warp & 3;         // warp within pair
        const int g    = lane >> 2;
        const int t4   = lane & 3;
        const int warpM = (w4 >> 1) * 32;
        const int warpN = (w4 & 1) * 32;
        const float* Bp = Bs0 + p * TILE_F;
        const int   ntp = p ? nt1 : nt0;

        float acc[2][4][4];
        #pragma unroll
        for (int mi = 0; mi < 2; ++mi)
            #pragma unroll
            for (int ni = 0; ni < 4; ++ni)
                #pragma unroll
                for (int q = 0; q < 4; ++q) acc[mi][ni][q] = 0.0f;

        #pragma unroll
        for (int kk = 0; kk < D; kk += 8) {
            uint32_t a[2][4], b[4][2];
            #pragma unroll
            for (int mi = 0; mi < 2; ++mi) {
                const float* ap = As + (warpM + mi * 16 + g) * A_PITCH + kk + t4;
                a[mi][0] = __float_as_uint(ap[0]);
                a[mi][1] = __float_as_uint(ap[8 * A_PITCH]);
                a[mi][2] = __float_as_uint(ap[4]);
                a[mi][3] = __float_as_uint(ap[8 * A_PITCH + 4]);
            }
            #pragma unroll
            for (int ni = 0; ni < 4; ++ni) {
                const float* bp = Bp + (warpN + ni * 8 + g) * A_PITCH + kk + t4;
                b[ni][0] = __float_as_uint(bp[0]);
                b[ni][1] = __float_as_uint(bp[4]);
            }
            #pragma unroll
            for (int mi = 0; mi < 2; ++mi)
                #pragma unroll
                for (int ni = 0; ni < 4; ++ni)
                    MMA_TF32(acc[mi][ni], a[mi], b[ni]);
        }

        __syncthreads();   // all warps done reading As/Bs; Ss overlays As

        float* Sp = sm + p * SS_F;
        #pragma unroll
        for (int mi = 0; mi < 2; ++mi) {
            #pragma unroll
            for (int ni = 0; ni < 4; ++ni) {
                int r0 = warpM + mi * 16 + g;
                int r1 = r0 + 8;
                int c0 = warpN + ni * 8 + 2 * t4;
                bool cv0 = (c0 < ntp), cv1 = (c0 + 1 < ntp);
                Sp[r0 * S_PITCH + c0]     = (r0 < nv && cv0) ? acc[mi][ni][0] : -1.0f;
                Sp[r0 * S_PITCH + c0 + 1] = (r0 < nv && cv1) ? acc[mi][ni][1] : -1.0f;
                Sp[r1 * S_PITCH + c0]     = (r1 < nv && cv0) ? acc[mi][ni][2] : -1.0f;
                Sp[r1 * S_PITCH + c0 + 1] = (r1 < nv && cv1) ? acc[mi][ni][3] : -1.0f;
            }
        }
    }
    __syncthreads();

    // ---- Phase 3: sparsemax. tid layout: [pair(1)][role(1)][r(6)] ----
    {
        const int p    = tid >> 7;
        const int role = (tid >> 6) & 1;   // 0 = rows (region->word), 1 = cols
        const int r    = tid & 63;
        const float* Sp = sm + p * SS_F;
        const int   ntp = p ? nt1 : nt0;

        const float* bp = role ? (Sp + r) : (Sp + r * S_PITCH);
        const int   str = role ? S_PITCH : 1;

        float z[64];
        #pragma unroll
        for (int j = 0; j < 64; ++j) z[j] = bp[j * str];

        float s0 = 0.f, s1 = 0.f, s2 = 0.f, s3 = 0.f;
        #pragma unroll
        for (int j = 0; j < 64; j += 4) {
            s0 += z[j]; s1 += z[j + 1]; s2 += z[j + 2]; s3 += z[j + 3];
        }
        float tau = ((s0 + s1) + (s2 + s3) - 1.0f) * (1.0f / 64.0f);
        int k = 64;

        // Michelot fixed-point (support is nested, tau nondecreasing)
        #pragma unroll 1
        for (int it = 0; it < 64; ++it) {
            float a0 = 0.f, a1 = 0.f, a2 = 0.f, a3 = 0.f;
            int c = 0;
            #pragma unroll
            for (int j = 0; j < 64; j += 4) {
                if (z[j]     > tau) { a0 += z[j];     c++; }
                if (z[j + 1] > tau) { a1 += z[j + 1]; c++; }
                if (z[j + 2] > tau) { a2 += z[j + 2]; c++; }
                if (z[j + 3] > tau) { a3 += z[j + 3]; c++; }
            }
            if (c == k) break;
            k = c;
            tau = __fdividef(((a0 + a1) + (a2 + a3)) - 1.0f, (float)c);
        }

        float a0 = 0.f, a1 = 0.f, a2 = 0.f, a3 = 0.f;
        #pragma unroll
        for (int j = 0; j < 64; j += 4) {
            float p0 = z[j] - tau,     p1 = z[j + 1] - tau;
            float p2 = z[j + 2] - tau, p3 = z[j + 3] - tau;
            if (p0 > 0.f) a0 = fmaf(p0, z[j],     a0);
            if (p1 > 0.f) a1 = fmaf(p1, z[j + 1], a1);
            if (p2 > 0.f) a2 = fmaf(p2, z[j + 2], a2);
            if (p3 > 0.f) a3 = fmaf(p3, z[j + 3], a3);
        }
        float rsum = (a0 + a1) + (a2 + a3);

        bool valid = role ? (r < ntp) : (r < nv);
        red[tid] = valid ? rsum : 0.0f;
    }
    __syncthreads();

    // ---- Phase 4: masked means; warp 0 -> pair 0, warp 1 -> pair 1 ----
    if (tid < 64) {
        const int wp   = tid >> 5;
        const int lane = tid & 31;
        const float* rp = red + wp * 128;
        float v = rp[lane]      + rp[lane + 32];
        float w = rp[64 + lane] + rp[96 + lane];
        #pragma unroll
        for (int o = 16; o; o >>= 1) {
            v += __shfl_down_sync(0xffffffffu, v, o);
            w += __shfl_down_sync(0xffffffffu, w, o);
        }
        if (lane == 0) {
            int nt = wp ? nt1 : nt0;
            out[i * B_CAP + t0 + wp] = 0.5f * (v / (float)nv + w / (float)nt);
        }
    }
}

extern "C" void kernel_launch(void* const* d_in, const int* in_sizes, int n_in,
                              void* d_out, int out_size)
{
    // metadata order: img_cls, imgs, cap_cls, caps, img_lens, cap_lens
    const float* imgs     = (const float*)d_in[1];
    const float* caps     = (const float*)d_in[3];
    const int*   img_lens = (const int*)d_in[4];
    const int*   cap_lens = (const int*)d_in[5];
    float*       out      = (float*)d_out;

    cudaFuncSetAttribute(select_kernel,
                         cudaFuncAttributeMaxDynamicSharedMemorySize, SMEM_BYTES);

    dim3 grid(B_CAP / 2, B_IMG);
    select_kernel<<<grid, 256, SMEM_BYTES>>>(imgs, caps, img_lens, cap_lens, out);
}